// round 7
// baseline (speedup 1.0000x reference)
#include <cuda_runtime.h>

// RNN: B=4096, T=512, I=1, H=16, O=1
//   h_t = tanh(x_t*w_ih + b_ih + b_hh + W_hh h_{t-1}), h_0=0
//   out[b] = dot(h_T, w_fc) + b_fc
//
// Wall-time model: all 4096 elements run concurrently; wall = 512 * C where
// C = per-step dependency chain. R7 shortens C:
//  - h broadcast via smem WITHOUT __syncwarp: one warp = one in-order
//    instruction stream through one LSU FIFO, so the warp's STS commits
//    before its later LDS reads (no-store-forward HW stalls the load).
//    Saves ~23cyc WARPSYNC per step. Single buffer (no cross-lane race
//    possible within one warp's stream).
//  - Packed f32x2 dot: 4 accumulators depth 2 + 2 add2 levels; the x-term
//    is pre-packed into accumulator 0's addend (off critical path).
//  - Recurrence in r-space: r = 1/(1+2^(K*a)), K=2*log2(e), h=1-2r, with
//    (1-2r), K folded into packed weights (proven rel_err ~8e-7).
//  - x staged in smem once per warp; LDS.128 per 4 steps.

#define RNN_B 4096
#define RNN_T 512
#define RNN_H 16
#define XROW (RNN_T + 4)   // x row pad: groups' reads on different banks
#define HSTR 16            // h row stride in floats (64B): group1 -> banks 16-31

__device__ __forceinline__ float ex2_approx(float x) {
    float y; asm("ex2.approx.f32 %0, %1;" : "=f"(y) : "f"(x)); return y;
}
__device__ __forceinline__ float rcp_approx(float x) {
    float y; asm("rcp.approx.f32 %0, %1;" : "=f"(y) : "f"(x)); return y;
}
__device__ __forceinline__ unsigned long long mul2(unsigned long long a, unsigned long long b) {
    unsigned long long d; asm("mul.rn.f32x2 %0, %1, %2;" : "=l"(d) : "l"(a), "l"(b)); return d;
}
__device__ __forceinline__ unsigned long long fma2(unsigned long long a, unsigned long long b, unsigned long long c) {
    unsigned long long d; asm("fma.rn.f32x2 %0, %1, %2, %3;" : "=l"(d) : "l"(a), "l"(b), "l"(c)); return d;
}
__device__ __forceinline__ unsigned long long add2(unsigned long long a, unsigned long long b) {
    unsigned long long d; asm("add.rn.f32x2 %0, %1, %2;" : "=l"(d) : "l"(a), "l"(b)); return d;
}
__device__ __forceinline__ unsigned long long packf2(float lo, float hi) {
    unsigned long long d; asm("mov.b64 %0, {%1, %2};" : "=l"(d) : "f"(lo), "f"(hi)); return d;
}
__device__ __forceinline__ float2 unpackf2(unsigned long long p) {
    float lo, hi; asm("mov.b64 {%0, %1}, %2;" : "=f"(lo), "=f"(hi) : "l"(p));
    return make_float2(lo, hi);
}
__device__ __forceinline__ void lds_v2u64(unsigned saddr, unsigned long long& a, unsigned long long& b) {
    asm volatile("ld.shared.v2.u64 {%0, %1}, [%2];" : "=l"(a), "=l"(b) : "r"(saddr));
}
__device__ __forceinline__ void sts_f32(unsigned saddr, float v) {
    asm volatile("st.shared.f32 [%0], %1;" :: "r"(saddr), "f"(v));
}

__global__ __launch_bounds__(32) void rnn_scan_kernel(
    const float* __restrict__ x,      // [B, T, 1]
    const float* __restrict__ w_ih,   // [H]
    const float* __restrict__ w_hh,   // [H, H]
    const float* __restrict__ b_ih,   // [H]
    const float* __restrict__ b_hh,   // [H]
    const float* __restrict__ w_fc,   // [H]
    const float* __restrict__ b_fc,   // [1]
    float* __restrict__ out)          // [B]
{
    __shared__ __align__(16) float sx[2 * XROW];    // 2 sequences of x
    __shared__ __align__(16) float hb[2 * HSTR];    // r for both elements

    const int warp = blockIdx.x;      // one warp per block
    const int lane = threadIdx.x;     // 0..31
    const int sub  = lane >> 4;       // batch element within warp (0/1)
    const int j    = lane & 15;       // hidden row owned by this lane

    const int b = warp * 2 + sub;     // < 4096

    // ---- Preload this warp's 2 contiguous x sequences (4KB) into smem. ----
    {
        const float4* src = reinterpret_cast<const float4*>(x + (long)warp * 2 * RNN_T);
        #pragma unroll
        for (int i = 0; i < 8; i++) {
            const int idx = i * 32 + lane;        // float4 index 0..255
            const float4 v = src[idx];
            const int f   = idx * 4;
            const int row = f >> 9;               // /512
            const int col = f & 511;
            *reinterpret_cast<float4*>(&sx[row * XROW + col]) = v;
        }
    }

    const float K = 2.8853900817779268f; // 2*log2(e)

    // Packed folded weights: wp[k] = (-2K*w[j][2k], -2K*w[j][2k+1])
    unsigned long long wp[8];
    float wsum = 0.0f;
    {
        const float4* w4 = reinterpret_cast<const float4*>(w_hh + j * RNN_H);
        #pragma unroll
        for (int q = 0; q < 4; q++) {
            float4 rw = w4[q];
            wsum += (rw.x + rw.y) + (rw.z + rw.w);
            wp[q * 2 + 0] = packf2(-2.0f * K * rw.x, -2.0f * K * rw.y);
            wp[q * 2 + 1] = packf2(-2.0f * K * rw.z, -2.0f * K * rw.w);
        }
    }
    const float wihK  = K * w_ih[j];
    const float biasK = K * (b_ih[j] + b_hh[j] + wsum);

    // Shared addresses: element sub's r vector at hb[sub*HSTR ..+16).
    const unsigned rbase = (unsigned)__cvta_generic_to_shared(&hb[sub * HSTR]);
    const unsigned waddr = rbase + 4u * j;

    // Init r0 = 0.5 (h0 = 0). Same-warp STS->LDS ordering covers visibility.
    sts_f32(waddr, 0.5f);
    __syncwarp();

    const float4* sx4 = reinterpret_cast<const float4*>(&sx[sub * XROW]);

    float r = 0.5f;

    #pragma unroll 1
    for (int t4 = 0; t4 < RNN_T / 4; t4++) {
        const float4 xv = sx4[t4];    // broadcast LDS.128 within each group
        const float xs[4] = {xv.x, xv.y, xv.z, xv.w};
        #pragma unroll
        for (int s = 0; s < 4; s++) {
            // x-term, ready before the loads land; packed as acc0 seed.
            const float accQ = fmaf(xs[s], wihK, biasK);
            const unsigned long long seed = packf2(accQ, 0.0f);

            // Gather 16 r values as 8 packed f32x2 pairs (in-order LSU:
            // these see the previous iteration's STS without a barrier).
            unsigned long long rp0, rp1, rp2, rp3, rp4, rp5, rp6, rp7;
            lds_v2u64(rbase +  0, rp0, rp1);
            lds_v2u64(rbase + 16, rp2, rp3);
            lds_v2u64(rbase + 32, rp4, rp5);
            lds_v2u64(rbase + 48, rp6, rp7);

            // 4 packed accumulators, depth 2, then 2 add2 levels.
            unsigned long long a0 = fma2(wp[0], rp0, seed);
            unsigned long long a1 = mul2(wp[1], rp1);
            unsigned long long a2 = mul2(wp[2], rp2);
            unsigned long long a3 = mul2(wp[3], rp3);
            a0 = fma2(wp[4], rp4, a0);
            a1 = fma2(wp[5], rp5, a1);
            a2 = fma2(wp[6], rp6, a2);
            a3 = fma2(wp[7], rp7, a3);
            a0 = add2(a0, a1);
            a2 = add2(a2, a3);
            a0 = add2(a0, a2);
            const float2 pr = unpackf2(a0);
            const float acc = pr.x + pr.y;

            // r = 1/(1 + 2^acc)
            r = rcp_approx(1.0f + ex2_approx(acc));
            sts_f32(waddr, r);
        }
    }

    // h = 1 - 2r; out[b] = sum_j h[j]*w_fc[j] + b_fc
    const float h = fmaf(-2.0f, r, 1.0f);
    float v = h * w_fc[j];
    #pragma unroll
    for (int off = 8; off; off >>= 1)
        v += __shfl_xor_sync(0xffffffffu, v, off, 16);
    if (j == 0)
        out[b] = v + b_fc[0];
}

extern "C" void kernel_launch(void* const* d_in, const int* in_sizes, int n_in,
                              void* d_out, int out_size) {
    const float* x    = (const float*)d_in[0];
    const float* w_ih = (const float*)d_in[1];
    const float* w_hh = (const float*)d_in[2];
    const float* b_ih = (const float*)d_in[3];
    const float* b_hh = (const float*)d_in[4];
    const float* w_fc = (const float*)d_in[5];
    const float* b_fc = (const float*)d_in[6];
    float* out = (float*)d_out;

    // 2048 single-warp blocks; 2 batch elements per warp.
    rnn_scan_kernel<<<RNN_B / 2, 32>>>(x, w_ih, w_hh, b_ih, b_hh, w_fc, b_fc, out);
}